// round 5
// baseline (speedup 1.0000x reference)
#include <cuda_runtime.h>
#include <cstdint>

#define B   32
#define H   384
#define W   640
#define C   128
#define HS  96      // H / SCALE
#define WS  160     // W / SCALE
#define FW  30
#define THRESH 0.015f
#define TOPK 2000
#define TBLOCKS 2048   // persistent transpose grid
#define CHUNK 4096     // pixels per select chunk (1024 thr * 4 px)
#define NFAST 8        // chunks counted in the wide fast path

// Static device scratch (allocation-free rule: __device__ globals allowed)
__device__ float d_hwc[(size_t)B * HS * WS * C];
__device__ int   d_idx[B * TOPK];
__device__ int   d_cnt[B * NFAST];
__device__ int   d_rmin[B];
__device__ int   d_rmax[B];

// ---------------------------------------------------------------------------
// Shared chunk-emission helper: processes pixels [pixBase, pixBase+CHUNK) of
// batch b's in-region row-major stream; hits get ordered global rank
// base+localRank; ranks < TOPK are emitted. Returns the chunk's hit count.
// Requires all 1024 threads; uses the caller's shared scratch.
// ---------------------------------------------------------------------------
__device__ __forceinline__ int emit_chunk(
    const float* __restrict__ pb, int rowW, int totalPix, int pixBase,
    int base, int b, float rv, float* __restrict__ pts_out,
    int* sWarpBase, int* sTotal, int* sRmin, int* sRmax)
{
    const int tid  = threadIdx.x;
    const int warp = tid >> 5;
    const int lane = tid & 31;

    unsigned pmask = 0;
    int rr[4], cc[4];
    const int pix0 = pixBase + 4 * tid;
    if (rowW > 0 && pix0 < totalPix) {
        const int rq = pix0 / rowW;
        int ri = FW + rq, ci = FW + pix0 - rq * rowW;
        #pragma unroll
        for (int j = 0; j < 4; ++j) {
            rr[j] = ri; cc[j] = ci;
            if ((pix0 + j) < totalPix && pb[(size_t)ri * W + ci] > THRESH)
                pmask |= (1u << j);
            if (++ci >= FW + rowW) { ci = FW; ++ri; }
        }
    }
    const int cnt = __popc(pmask);

    int incl = cnt;
    #pragma unroll
    for (int d = 1; d < 32; d <<= 1) {
        int y = __shfl_up_sync(0xffffffffu, incl, d);
        if (lane >= d) incl += y;
    }
    if (lane == 31) sWarpBase[warp] = incl;
    __syncthreads();
    if (tid < 32) {
        int v = sWarpBase[tid];
        int x = v;
        #pragma unroll
        for (int d = 1; d < 32; d <<= 1) {
            int y = __shfl_up_sync(0xffffffffu, x, d);
            if (tid >= d) x += y;
        }
        sWarpBase[tid] = x - v;
        if (tid == 31) *sTotal = x;
    }
    __syncthreads();
    int pos = base + sWarpBase[warp] + (incl - cnt);

    int myRmin = 0x7fffffff, myRmax = -1;
    #pragma unroll
    for (int j = 0; j < 4; ++j) {
        if (pmask & (1u << j)) {
            if (pos < TOPK) {
                d_idx[b * TOPK + pos] = rr[j] * W + cc[j];
                ((float2*)pts_out)[(size_t)b * TOPK + pos] =
                    make_float2((float)cc[j] / rv, (float)rr[j] / rv);
                if (rr[j] < myRmin) myRmin = rr[j];
                if (rr[j] > myRmax) myRmax = rr[j];
            }
            ++pos;
        }
    }
    if (myRmax >= 0) {
        atomicMin(sRmin, myRmin);
        atomicMax(sRmax, myRmax);
    }
    const int total = *sTotal;
    __syncthreads();   // protect shared scratch for next call
    return total;
}

// ---------------------------------------------------------------------------
// Kernel 1a: wide hit counting over the first NFAST chunks per batch.
// grid (B, NFAST), block 1024. Also initializes the per-batch row range.
// ---------------------------------------------------------------------------
__global__ __launch_bounds__(1024) void count_kernel(
    const float* __restrict__ prob,
    const int* __restrict__ rshape_raw)
{
    const int b   = blockIdx.x;
    const int ck  = blockIdx.y;
    const int tid = threadIdx.x;
    const int warp = tid >> 5;
    const int lane = tid & 31;

    if (ck == 0 && tid == 0) { d_rmin[b] = 0x7fffffff; d_rmax[b] = -1; }

    const int stride = (rshape_raw[1] == 0) ? 2 : 1;
    const int r0 = rshape_raw[(2 * b)     * stride];
    const int r1 = rshape_raw[(2 * b + 1) * stride];
    const int rowW     = r1 - 2 * FW;
    const int totalPix = (r0 - 2 * FW) * rowW;
    const float* pb = prob + (size_t)b * H * W;

    int cnt = 0;
    const int pix0 = ck * CHUNK + 4 * tid;
    if (rowW > 0 && pix0 < totalPix) {
        const int rq = pix0 / rowW;
        int ri = FW + rq, ci = FW + pix0 - rq * rowW;
        #pragma unroll
        for (int j = 0; j < 4; ++j) {
            if ((pix0 + j) < totalPix && pb[(size_t)ri * W + ci] > THRESH) ++cnt;
            if (++ci >= FW + rowW) { ci = FW; ++ri; }
        }
    }
    #pragma unroll
    for (int d = 16; d > 0; d >>= 1)
        cnt += __shfl_down_sync(0xffffffffu, cnt, d);

    __shared__ int sW[32];
    if (lane == 0) sW[warp] = cnt;
    __syncthreads();
    if (tid < 32) {
        int v = sW[tid];
        #pragma unroll
        for (int d = 16; d > 0; d >>= 1)
            v += __shfl_down_sync(0xffffffffu, v, d);
        if (tid == 0) d_cnt[b * NFAST + ck] = v;
    }
}

// ---------------------------------------------------------------------------
// Kernel 1b: wide ordered emission. grid (B, NFAST), block 1024.
// Each block derives its chunk's rank base from the counts; non-relevant
// blocks exit. The last chunk's block finishes serially if the fast region
// didn't reach TOPK (general fallback) and fills the invalid tail.
// ---------------------------------------------------------------------------
__global__ __launch_bounds__(1024) void emit_kernel(
    const float* __restrict__ prob,
    const float* __restrict__ ratio,
    const int* __restrict__ rshape_raw,
    float* __restrict__ pts_out)
{
    const int b   = blockIdx.x;
    const int ck  = blockIdx.y;
    const int tid = threadIdx.x;

    __shared__ int sCnt[NFAST];
    __shared__ int sWarpBase[32];
    __shared__ int sTotal;
    __shared__ int sRmin, sRmax;
    if (tid == 0) { sRmin = 0x7fffffff; sRmax = -1; }
    if (tid < NFAST) sCnt[tid] = d_cnt[b * NFAST + tid];
    __syncthreads();

    int chunkStart = 0, grand = 0;
    #pragma unroll
    for (int j = 0; j < NFAST; ++j) {
        if (j < ck) chunkStart += sCnt[j];
        grand += sCnt[j];
    }
    const bool finisher = (ck == NFAST - 1);
    if (!finisher && chunkStart >= TOPK) return;

    const int stride = (rshape_raw[1] == 0) ? 2 : 1;
    const int r0 = rshape_raw[(2 * b)     * stride];
    const int r1 = rshape_raw[(2 * b + 1) * stride];
    const int rowW     = r1 - 2 * FW;
    const int totalPix = (r0 - 2 * FW) * rowW;
    const float rv = ratio[b];
    const float* pb = prob + (size_t)b * H * W;

    if (chunkStart < TOPK) {
        emit_chunk(pb, rowW, totalPix, ck * CHUNK, chunkStart, b, rv,
                   pts_out, sWarpBase, &sTotal, &sRmin, &sRmax);
    }

    if (finisher) {
        int baseLoc = grand;
        for (int sw = NFAST * CHUNK; sw < totalPix && baseLoc < TOPK; sw += CHUNK) {
            baseLoc += emit_chunk(pb, rowW, totalPix, sw, baseLoc, b, rv,
                                  pts_out, sWarpBase, &sTotal, &sRmin, &sRmax);
        }
        const int fillFrom = (baseLoc < TOPK) ? baseLoc : TOPK;
        for (int k = fillFrom + tid; k < TOPK; k += 1024) {
            d_idx[b * TOPK + k] = -1;
            ((float2*)pts_out)[(size_t)b * TOPK + k] = make_float2(0.0f, 0.0f);
        }
    }

    __syncthreads();
    if (tid == 0 && sRmax >= 0) {
        atomicMin(&d_rmin[b], sRmin);
        atomicMax(&d_rmax[b], sRmax);
    }
}

// ---------------------------------------------------------------------------
// Kernel 2: persistent CHW -> HWC transpose over a compact task list.
// Task = (batch, feat row, tile); 20 tiles per row (5 x-tiles * 4 c-tiles).
// ---------------------------------------------------------------------------
__global__ __launch_bounds__(256) void transpose_kernel(const float* __restrict__ feat)
{
    __shared__ int sOff[B + 1];
    __shared__ int sYmin[B];
    __shared__ float tile[32][33];

    const int t0 = threadIdx.y * 32 + threadIdx.x;
    if (t0 == 0) {
        int acc = 0;
        #pragma unroll
        for (int b = 0; b < B; ++b) {
            const int rmax = d_rmax[b];
            int ymin = 0, n = 0;
            if (rmax >= 0) {
                ymin = d_rmin[b] >> 2;
                int ymaxr = (rmax >> 2) + 1;
                if (ymaxr > HS - 1) ymaxr = HS - 1;
                n = ymaxr - ymin + 1;
            }
            sOff[b] = acc;
            sYmin[b] = ymin;
            acc += n;
        }
        sOff[B] = acc;
    }
    __syncthreads();
    const int totalTasks = sOff[B] * 20;

    const int tx = threadIdx.x;  // 0..31
    const int ty = threadIdx.y;  // 0..7

    for (int t = blockIdx.x; t < totalTasks; t += TBLOCKS) {
        const int rowTask = t / 20;
        const int tileId  = t - rowTask * 20;
        int b = 0;
        while (sOff[b + 1] <= rowTask) ++b;        // uniform across block
        const int y  = sYmin[b] + (rowTask - sOff[b]);
        const int xt = tileId % 5;                 // 0..4 (x tiles of 32)
        const int ct = tileId / 5;                 // 0..3 (c tiles of 32)

        const float* src = feat + ((size_t)b * C) * (HS * WS) + (size_t)y * WS;
        #pragma unroll
        for (int i = 0; i < 4; ++i) {
            const int cc = ct * 32 + ty + i * 8;
            tile[ty + i * 8][tx] = src[(size_t)cc * (HS * WS) + xt * 32 + tx];
        }
        __syncthreads();
        float* dst = d_hwc + ((size_t)(b * HS + y) * WS) * C;
        #pragma unroll
        for (int i = 0; i < 4; ++i) {
            const int x = xt * 32 + ty + i * 8;
            dst[(size_t)x * C + ct * 32 + tx] = tile[tx][ty + i * 8];
        }
        __syncthreads();
    }
}

// ---------------------------------------------------------------------------
// Kernel 3: bilinear gather, vectorized float4.
// 32 points per block; 256 threads = 8 point-lanes x 32 channel-groups.
// ---------------------------------------------------------------------------
__global__ __launch_bounds__(256) void gather_kernel(float* __restrict__ des_out)
{
    const int b  = blockIdx.y;
    const int p0 = blockIdx.x * 32;
    const int cg = threadIdx.x & 31;   // channel group -> channels 4*cg..4*cg+3
    const int pl = threadIdx.x >> 5;   // point lane 0..7

    __shared__ int sIdx[32];
    if (threadIdx.x < 32) {
        const int p = p0 + threadIdx.x;
        sIdx[threadIdx.x] = (p < TOPK) ? d_idx[b * TOPK + p] : -1;
    }
    __syncthreads();

    #pragma unroll
    for (int i = 0; i < 4; ++i) {
        const int p = p0 + pl + i * 8;
        if (p >= TOPK) break;
        const int lin = sIdx[pl + i * 8];
        float4 v = make_float4(0.f, 0.f, 0.f, 0.f);
        if (lin >= 0) {
            const int y = lin / W;
            const int x = lin - y * W;
            const int x0 = x >> 2;
            const int y0 = y >> 2;
            const float fx = (float)(x & 3) * 0.25f;
            const float fy = (float)(y & 3) * 0.25f;
            const float4* base = (const float4*)(d_hwc +
                (((size_t)(b * HS + y0) * WS + x0) * C)) + cg;
            const float4 Ia = base[0];
            const float4 Ic = base[C / 4];
            const float4 Ib = base[(size_t)WS * C / 4];
            const float4 Id = base[(size_t)WS * C / 4 + C / 4];
            const float wa = (1.0f - fx) * (1.0f - fy);
            const float wb = (1.0f - fx) * fy;
            const float wc = fx * (1.0f - fy);
            const float wd = fx * fy;
            v.x = Ia.x * wa + Ib.x * wb + Ic.x * wc + Id.x * wd;
            v.y = Ia.y * wa + Ib.y * wb + Ic.y * wc + Id.y * wd;
            v.z = Ia.z * wa + Ib.z * wb + Ic.z * wc + Id.z * wd;
            v.w = Ia.w * wa + Ib.w * wb + Ic.w * wc + Id.w * wd;
        }
        ((float4*)des_out)[((size_t)b * TOPK + p) * (C / 4) + cg] = v;
    }
}

// ---------------------------------------------------------------------------
extern "C" void kernel_launch(void* const* d_in, const int* in_sizes, int n_in,
                              void* d_out, int out_size)
{
    const float* prob   = (const float*)d_in[0];      // [B,1,H,W]
    const float* feat   = (const float*)d_in[1];      // [B,C,HS,WS]
    const float* ratio  = (const float*)d_in[2];      // [B,1]
    const int*   rshape = (const int*)d_in[3];        // [B,2] int32 (or int64-packed)

    float* pts_out = (float*)d_out;                        // [B,TOPK,2]
    float* des_out = (float*)d_out + (size_t)B * TOPK * 2; // [B,TOPK,C]

    count_kernel<<<dim3(B, NFAST), 1024>>>(prob, rshape);
    emit_kernel<<<dim3(B, NFAST), 1024>>>(prob, ratio, rshape, pts_out);
    transpose_kernel<<<TBLOCKS, dim3(32, 8)>>>(feat);
    gather_kernel<<<dim3((TOPK + 31) / 32, B), 256>>>(des_out);
}